// round 2
// baseline (speedup 1.0000x reference)
#include <cuda_runtime.h>
#include <cuda_bf16.h>

#define N_NODES 384
#define HEIGHT  60
#define CCH     128
#define N_LAYERS 4
#define NODE_SZ (CCH * HEIGHT)          // 7680 floats per node
#define WT_SZ   (CCH * 256)             // 32768 per layer

// ---------------- device scratch (no allocations allowed) ----------------
__device__ float g_y[N_NODES * 2 * NODE_SZ];          // [n][part(a/b)][c][h]
__device__ float g_xb[2][N_NODES * NODE_SZ];          // ping-pong layer activations
__device__ float g_wt[N_LAYERS * WT_SZ];              // folded weights, [l][k][r], r in [0,256)
__device__ float g_M[N_LAYERS * CCH * 6];             // [l][c][f], f<5: M, f=5: b3
__device__ int   g_nbr[N_NODES * 16];                 // incoming edge ids per dst node
__device__ int   g_deg[N_NODES];

// ---------------- CSR (deterministic, per-node sequential scan) ----------
__global__ void csr_kernel(const int* __restrict__ ei, int E) {
    int n = threadIdx.x;
    if (n >= N_NODES) return;
    const int* dst = ei + E;   // edge_index[1]
    int cnt = 0;
    for (int e = 0; e < E; e++) {
        if (dst[e] == n) {
            if (cnt < 16) g_nbr[n * 16 + cnt] = e;
            cnt++;
        }
    }
    g_deg[n] = cnt < 16 ? cnt : 16;
}

// ---------------- weight folding ----------------
// conv_w: (L, C, 3C). Wt[l][k][r]: r<128 -> cw1[r][k]-cw2[r][k]; r>=128 -> cw2[r-128][k]
// M[l][c][f<5] = sum_k cw3[c][k]*ew[k][f];  M[l][c][5] = sum_k cw3[c][k]*eb[k]
__global__ void prep_kernel(const float* __restrict__ conv_w,
                            const float* __restrict__ edge_w,
                            const float* __restrict__ edge_b) {
    int l = blockIdx.x, tid = threadIdx.x;
    const float* cw = conv_w + l * (CCH * 3 * CCH);
    for (int i = tid; i < WT_SZ; i += 256) {
        int k = i >> 8, r = i & 255;
        float v;
        if (r < 128) v = cw[r * 384 + k] - cw[r * 384 + 128 + k];
        else         v = cw[(r - 128) * 384 + 128 + k];
        g_wt[l * WT_SZ + i] = v;
    }
    if (tid < CCH) {
        int c = tid;
        const float* cw3 = cw + c * 384 + 256;
        const float* ewl = edge_w + l * (CCH * 5);
        const float* ebl = edge_b + l * CCH;
        float m0 = 0.f, m1 = 0.f, m2 = 0.f, m3 = 0.f, m4 = 0.f, m5 = 0.f;
        for (int k = 0; k < CCH; k++) {
            float w = cw3[k];
            m0 += w * ewl[k * 5 + 0];
            m1 += w * ewl[k * 5 + 1];
            m2 += w * ewl[k * 5 + 2];
            m3 += w * ewl[k * 5 + 3];
            m4 += w * ewl[k * 5 + 4];
            m5 += w * ebl[k];
        }
        float* Mp = g_M + l * (CCH * 6) + c * 6;
        Mp[0] = m0; Mp[1] = m1; Mp[2] = m2; Mp[3] = m3; Mp[4] = m4; Mp[5] = m5;
    }
}

// ---------------- node GEMM: y[n] (256 x 60) = Wt (256 x 128) @ x[n] (128 x 60) ---
// one CTA per node, 256 threads, 8x8 register tiles, fp32x2 packed FMA.
#define GEMM_SMEM ((CCH * 64 + 64 * 256) * 4)   // xs (padded to 64 cols) + ws chunk
__global__ __launch_bounds__(256, 2)
void gemm_node_kernel(const float* __restrict__ x0, int l) {
    extern __shared__ float sm[];
    float* xs = sm;                  // [128][64], cols 60..63 zero
    float* ws = sm + CCH * 64;       // [64][256] K-chunk of folded weights
    const float* xin = (l == 0) ? x0 : g_xb[(l + 1) & 1];
    const float* wt = g_wt + l * WT_SZ;
    int n = blockIdx.x, tid = threadIdx.x;
    const float* xn = xin + (size_t)n * NODE_SZ;

#pragma unroll 4
    for (int i = tid; i < CCH * 64; i += 256) {
        int k = i >> 6, h = i & 63;
        xs[i] = (h < HEIGHT) ? xn[k * HEIGHT + h] : 0.f;
    }

    int ct = tid & 31, ht = tid >> 5;
    int r0 = ct << 3, h0 = ht << 3;

    unsigned long long acc[8][4];
#pragma unroll
    for (int r = 0; r < 8; r++)
#pragma unroll
        for (int j = 0; j < 4; j++) acc[r][j] = 0ULL;

    for (int kc = 0; kc < 2; kc++) {
        __syncthreads();
        const float* wsrc = wt + kc * (64 * 256);
        for (int i = tid * 4; i < 64 * 256; i += 256 * 4)
            *(float4*)(ws + i) = *(const float4*)(wsrc + i);
        __syncthreads();

#pragma unroll 2
        for (int kk = 0; kk < 64; kk++) {
            int kb = ((kc << 6) + kk) << 6;
            ulonglong2 xv01 = *reinterpret_cast<const ulonglong2*>(xs + kb + h0);
            ulonglong2 xv23 = *reinterpret_cast<const ulonglong2*>(xs + kb + h0 + 4);
            unsigned long long xv[4] = {xv01.x, xv01.y, xv23.x, xv23.y};
            float4 wA = *reinterpret_cast<const float4*>(ws + (kk << 8) + r0);
            float4 wB = *reinterpret_cast<const float4*>(ws + (kk << 8) + r0 + 4);
            float wr[8] = {wA.x, wA.y, wA.z, wA.w, wB.x, wB.y, wB.z, wB.w};
#pragma unroll
            for (int r = 0; r < 8; r++) {
                unsigned long long wp;
                asm("mov.b64 %0, {%1, %2};" : "=l"(wp) : "f"(wr[r]), "f"(wr[r]));
#pragma unroll
                for (int j = 0; j < 4; j++)
                    asm("fma.rn.f32x2 %0, %1, %2, %0;"
                        : "+l"(acc[r][j]) : "l"(wp), "l"(xv[j]));
            }
        }
    }

#pragma unroll
    for (int r = 0; r < 8; r++) {
        int row = r0 + r;
        float o[8];
#pragma unroll
        for (int j = 0; j < 4; j++)
            asm("mov.b64 {%0, %1}, %2;" : "=f"(o[2 * j]), "=f"(o[2 * j + 1]) : "l"(acc[r][j]));
        float* yp = g_y + ((size_t)(n * 2 + (row >> 7))) * NODE_SZ + (row & 127) * HEIGHT + h0;
        *(float4*)yp = make_float4(o[0], o[1], o[2], o[3]);
        if (h0 < 56)
            *(float4*)(yp + 4) = make_float4(o[4], o[5], o[6], o[7]);
    }
}

// ---------------- edge phase: per-dst CTA -----------------------------------
// h_e = ya[dst] + yb[src] + es;  LayerNorm over (C,H); relu; accumulate; one write.
#define EDGE_SMEM ((3 * NODE_SZ + CCH + 32) * 4)
__global__ __launch_bounds__(256, 2)
void edge_kernel(const float* __restrict__ ea,
                 const float* __restrict__ lng,
                 const float* __restrict__ lnb,
                 const int* __restrict__ ei,
                 float* __restrict__ dout, int l) {
    extern __shared__ float sm[];
    float* ya  = sm;                       // 7680
    float* t   = sm + NODE_SZ;             // 7680
    float* acc = sm + 2 * NODE_SZ;         // 7680
    float* es  = sm + 3 * NODE_SZ;         // 128
    float* red = es + CCH;                 // 32

    int n = blockIdx.x, tid = threadIdx.x;
    const float* gl = lng + l * NODE_SZ;
    const float* bl = lnb + l * NODE_SZ;
    float* xout = (l == 3) ? dout : g_xb[l & 1];
    const float* yan = g_y + (size_t)(2 * n) * NODE_SZ;

    for (int i = tid; i < NODE_SZ; i += 256) {
        ya[i] = yan[i];
        acc[i] = 0.f;
    }
    int deg = g_deg[n];

    for (int j = 0; j < deg; j++) {
        int e = g_nbr[n * 16 + j];
        int s = ei[e];   // src = edge_index[0][e]
        __syncthreads();   // protects ya/acc init, t, es, red across iterations
        if (tid < CCH) {
            const float* Mp = g_M + l * (CCH * 6) + tid * 6;
            const float* eap = ea + e * 5;
            es[tid] = Mp[0] * eap[0] + Mp[1] * eap[1] + Mp[2] * eap[2]
                    + Mp[3] * eap[3] + Mp[4] * eap[4] + Mp[5];
        }
        __syncthreads();

        const float* yb = g_y + (size_t)(2 * s + 1) * NODE_SZ;
        float s1 = 0.f, s2 = 0.f;
#pragma unroll
        for (int it = 0; it < 30; it++) {
            int i = tid + (it << 8);
            float v = ya[i] + yb[i] + es[i / HEIGHT];
            t[i] = v;
            s1 += v;
            s2 += v * v;
        }
#pragma unroll
        for (int o = 16; o; o >>= 1) {
            s1 += __shfl_xor_sync(0xffffffffu, s1, o);
            s2 += __shfl_xor_sync(0xffffffffu, s2, o);
        }
        int wid = tid >> 5, lane = tid & 31;
        if (lane == 0) { red[wid] = s1; red[8 + wid] = s2; }
        __syncthreads();
        if (tid == 0) {
            float a = 0.f, b2 = 0.f;
#pragma unroll
            for (int w = 0; w < 8; w++) { a += red[w]; b2 += red[8 + w]; }
            float mu = a * (1.f / (float)NODE_SZ);
            float var = b2 * (1.f / (float)NODE_SZ) - mu * mu;
            red[16] = mu;
            red[17] = rsqrtf(var + 1e-5f);
        }
        __syncthreads();
        float mu = red[16], rs = red[17];
#pragma unroll
        for (int it = 0; it < 30; it++) {
            int i = tid + (it << 8);
            float v = (t[i] - mu) * rs * gl[i] + bl[i];
            acc[i] += fmaxf(v, 0.f);
        }
    }

    float* on = xout + (size_t)n * NODE_SZ;
    for (int i = tid; i < NODE_SZ; i += 256)
        on[i] = acc[i];
}

// ---------------- launch -----------------------------------------------------
extern "C" void kernel_launch(void* const* d_in, const int* in_sizes, int n_in,
                              void* d_out, int out_size) {
    const float* x   = (const float*)d_in[0];
    const float* ea  = (const float*)d_in[1];
    const float* ew  = (const float*)d_in[2];
    const float* eb  = (const float*)d_in[3];
    const float* cw  = (const float*)d_in[4];
    const float* lng = (const float*)d_in[5];
    const float* lnb = (const float*)d_in[6];
    const int*   ei  = (const int*)d_in[7];
    float* out = (float*)d_out;
    int E = in_sizes[7] / 2;     // edge_index is (2, E) — do NOT trust a hardcoded E

    cudaFuncSetAttribute(gemm_node_kernel, cudaFuncAttributeMaxDynamicSharedMemorySize, GEMM_SMEM);
    cudaFuncSetAttribute(edge_kernel, cudaFuncAttributeMaxDynamicSharedMemorySize, EDGE_SMEM);

    csr_kernel<<<1, N_NODES>>>(ei, E);
    prep_kernel<<<N_LAYERS, 256>>>(cw, ew, eb);
    for (int l = 0; l < N_LAYERS; l++) {
        gemm_node_kernel<<<N_NODES, 256, GEMM_SMEM>>>(x, l);
        edge_kernel<<<N_NODES, 256, EDGE_SMEM>>>(ea, lng, lnb, ei, out, l);
    }
}

// round 3
// speedup vs baseline: 1.1144x; 1.1144x over previous
#include <cuda_runtime.h>
#include <cuda_bf16.h>

#define N_NODES 384
#define HEIGHT  60
#define CCH     128
#define N_LAYERS 4
#define NODE_SZ (CCH * HEIGHT)          // 7680 floats per node
#define WT_SZ   (CCH * 256)             // 32768 per layer

// ---------------- device scratch (no allocations allowed) ----------------
__device__ float g_y[N_NODES * 2 * NODE_SZ];          // [n][part(a/b)][c][h]
__device__ float g_xb[2][N_NODES * NODE_SZ];          // ping-pong layer activations
__device__ float g_wt[N_LAYERS * WT_SZ];              // folded weights, [l][k][r], r in [0,256)
__device__ float g_M[N_LAYERS * CCH * 6];             // [l][c][f], f<5: M, f=5: b3
__device__ int   g_nbr[N_NODES * 16];                 // incoming edge ids per dst node
__device__ int   g_deg[N_NODES];

// ---------------- CSR (deterministic, per-node sequential scan) ----------
__global__ void csr_kernel(const int* __restrict__ ei, int E) {
    int n = threadIdx.x;
    if (n >= N_NODES) return;
    const int* dst = ei + E;   // edge_index[1]
    int cnt = 0;
    for (int e = 0; e < E; e++) {
        if (dst[e] == n) {
            if (cnt < 16) g_nbr[n * 16 + cnt] = e;
            cnt++;
        }
    }
    g_deg[n] = cnt < 16 ? cnt : 16;
}

// ---------------- weight folding ----------------
__global__ void prep_kernel(const float* __restrict__ conv_w,
                            const float* __restrict__ edge_w,
                            const float* __restrict__ edge_b) {
    int l = blockIdx.x, tid = threadIdx.x;
    const float* cw = conv_w + l * (CCH * 3 * CCH);
    for (int i = tid; i < WT_SZ; i += 256) {
        int k = i >> 8, r = i & 255;
        float v;
        if (r < 128) v = cw[r * 384 + k] - cw[r * 384 + 128 + k];
        else         v = cw[(r - 128) * 384 + 128 + k];
        g_wt[l * WT_SZ + i] = v;
    }
    if (tid < CCH) {
        int c = tid;
        const float* cw3 = cw + c * 384 + 256;
        const float* ewl = edge_w + l * (CCH * 5);
        const float* ebl = edge_b + l * CCH;
        float m0 = 0.f, m1 = 0.f, m2 = 0.f, m3 = 0.f, m4 = 0.f, m5 = 0.f;
        for (int k = 0; k < CCH; k++) {
            float w = cw3[k];
            m0 += w * ewl[k * 5 + 0];
            m1 += w * ewl[k * 5 + 1];
            m2 += w * ewl[k * 5 + 2];
            m3 += w * ewl[k * 5 + 3];
            m4 += w * ewl[k * 5 + 4];
            m5 += w * ebl[k];
        }
        float* Mp = g_M + l * (CCH * 6) + c * 6;
        Mp[0] = m0; Mp[1] = m1; Mp[2] = m2; Mp[3] = m3; Mp[4] = m4; Mp[5] = m5;
    }
}

// ---------------- node GEMM: y[n] (256 x 60) = Wt (256 x 128) @ x[n] (128 x 60) ---
// one CTA per node, 256 threads. Lane owns rows {lane, lane+32, ..., lane+224}
// -> weight LDS are conflict-free (consecutive lanes, consecutive addresses).
// Warp owns 8 h-columns -> x LDS are warp-broadcast. fp32x2 packed FMA.
#define GEMM_SMEM ((CCH * 64 + 64 * 256) * 4)   // xs (padded to 64 cols) + ws chunk
__global__ __launch_bounds__(256, 2)
void gemm_node_kernel(const float* __restrict__ x0, int l) {
    extern __shared__ float sm[];
    float* xs = sm;                  // [128][64], cols 60..63 zero
    float* ws = sm + CCH * 64;       // [64][256] K-chunk of folded weights
    const float* xin = (l == 0) ? x0 : g_xb[(l + 1) & 1];
    const float* wt = g_wt + l * WT_SZ;
    int n = blockIdx.x, tid = threadIdx.x;
    const float* xn = xin + (size_t)n * NODE_SZ;

#pragma unroll 4
    for (int i = tid; i < CCH * 64; i += 256) {
        int k = i >> 6, h = i & 63;
        xs[i] = (h < HEIGHT) ? xn[k * HEIGHT + h] : 0.f;
    }

    int lane = tid & 31, wid = tid >> 5;
    int h0 = wid << 3;

    unsigned long long acc[8][4];
#pragma unroll
    for (int r = 0; r < 8; r++)
#pragma unroll
        for (int j = 0; j < 4; j++) acc[r][j] = 0ULL;

    for (int kc = 0; kc < 2; kc++) {
        __syncthreads();
        const float* wsrc = wt + kc * (64 * 256);
        for (int i = tid * 4; i < 64 * 256; i += 256 * 4)
            *(float4*)(ws + i) = *(const float4*)(wsrc + i);
        __syncthreads();

#pragma unroll 2
        for (int kk = 0; kk < 64; kk++) {
            int kb = ((kc << 6) + kk) << 6;
            ulonglong2 xv01 = *reinterpret_cast<const ulonglong2*>(xs + kb + h0);
            ulonglong2 xv23 = *reinterpret_cast<const ulonglong2*>(xs + kb + h0 + 4);
            unsigned long long xv[4] = {xv01.x, xv01.y, xv23.x, xv23.y};
            const float* wrow = ws + (kk << 8) + lane;
#pragma unroll
            for (int r = 0; r < 8; r++) {
                float w = wrow[r << 5];        // conflict-free scalar LDS
                unsigned long long wp;
                asm("mov.b64 %0, {%1, %2};" : "=l"(wp) : "f"(w), "f"(w));
#pragma unroll
                for (int j = 0; j < 4; j++)
                    asm("fma.rn.f32x2 %0, %1, %2, %0;"
                        : "+l"(acc[r][j]) : "l"(wp), "l"(xv[j]));
            }
        }
    }

#pragma unroll
    for (int r = 0; r < 8; r++) {
        int row = lane + (r << 5);
        float o[8];
#pragma unroll
        for (int j = 0; j < 4; j++)
            asm("mov.b64 {%0, %1}, %2;" : "=f"(o[2 * j]), "=f"(o[2 * j + 1]) : "l"(acc[r][j]));
        float* yp = g_y + ((size_t)(n * 2 + (row >> 7))) * NODE_SZ + (row & 127) * HEIGHT + h0;
        *(float4*)yp = make_float4(o[0], o[1], o[2], o[3]);
        if (h0 < 56)
            *(float4*)(yp + 4) = make_float4(o[4], o[5], o[6], o[7]);
    }
}

// ---------------- edge phase: per-dst CTA, register-resident -----------------
// h_e = ya[dst] + yb[src] + es;  LayerNorm over (C,H); relu; accumulate.
__global__ __launch_bounds__(256, 2)
void edge_kernel(const float* __restrict__ ea,
                 const float* __restrict__ lng,
                 const float* __restrict__ lnb,
                 const int* __restrict__ ei,
                 float* __restrict__ dout, int l) {
    __shared__ float es[CCH];
    __shared__ float red[16];

    int n = blockIdx.x, tid = threadIdx.x;
    const float* gl = lng + l * NODE_SZ;
    const float* bl = lnb + l * NODE_SZ;
    float* xout = (l == 3) ? dout : g_xb[l & 1];
    const float* yan = g_y + (size_t)(2 * n) * NODE_SZ;

    float ya[30], acc[30], t[30];
#pragma unroll
    for (int it = 0; it < 30; it++) {
        ya[it] = yan[tid + (it << 8)];
        acc[it] = 0.f;
    }
    int deg = g_deg[n];

    for (int j = 0; j < deg; j++) {
        int e = g_nbr[n * 16 + j];
        int s = ei[e];   // src = edge_index[0][e]
        if (tid < CCH) {
            const float* Mp = g_M + l * (CCH * 6) + tid * 6;
            const float* eap = ea + e * 5;
            es[tid] = fmaf(Mp[0], eap[0], fmaf(Mp[1], eap[1], fmaf(Mp[2], eap[2],
                      fmaf(Mp[3], eap[3], fmaf(Mp[4], eap[4], Mp[5])))));
        }
        __syncthreads();   // es visible; also orders red reuse across edges

        const float* yb = g_y + (size_t)(2 * s + 1) * NODE_SZ;
        float s1 = 0.f, s2 = 0.f;
#pragma unroll
        for (int it = 0; it < 30; it++) {
            int i = tid + (it << 8);
            float v = ya[it] + yb[i] + es[i / HEIGHT];
            t[it] = v;
            s1 += v;
            s2 += v * v;
        }
#pragma unroll
        for (int o = 16; o; o >>= 1) {
            s1 += __shfl_xor_sync(0xffffffffu, s1, o);
            s2 += __shfl_xor_sync(0xffffffffu, s2, o);
        }
        int wid = tid >> 5, lane = tid & 31;
        if (lane == 0) { red[wid] = s1; red[8 + wid] = s2; }
        __syncthreads();
        float a = 0.f, b2 = 0.f;
#pragma unroll
        for (int w = 0; w < 8; w++) { a += red[w]; b2 += red[8 + w]; }
        float mu = a * (1.f / (float)NODE_SZ);
        float rs = rsqrtf(b2 * (1.f / (float)NODE_SZ) - mu * mu + 1e-5f);
#pragma unroll
        for (int it = 0; it < 30; it++) {
            int i = tid + (it << 8);
            float v = (t[it] - mu) * rs * gl[i] + bl[i];
            acc[it] += fmaxf(v, 0.f);
        }
    }

    float* on = xout + (size_t)n * NODE_SZ;
#pragma unroll
    for (int it = 0; it < 30; it++)
        on[tid + (it << 8)] = acc[it];
}

// ---------------- launch -----------------------------------------------------
extern "C" void kernel_launch(void* const* d_in, const int* in_sizes, int n_in,
                              void* d_out, int out_size) {
    const float* x   = (const float*)d_in[0];
    const float* ea  = (const float*)d_in[1];
    const float* ew  = (const float*)d_in[2];
    const float* eb  = (const float*)d_in[3];
    const float* cw  = (const float*)d_in[4];
    const float* lng = (const float*)d_in[5];
    const float* lnb = (const float*)d_in[6];
    const int*   ei  = (const int*)d_in[7];
    float* out = (float*)d_out;
    int E = in_sizes[7] / 2;     // edge_index is (2, E)

    cudaFuncSetAttribute(gemm_node_kernel, cudaFuncAttributeMaxDynamicSharedMemorySize, GEMM_SMEM);

    csr_kernel<<<1, N_NODES>>>(ei, E);
    prep_kernel<<<N_LAYERS, 256>>>(cw, ew, eb);
    for (int l = 0; l < N_LAYERS; l++) {
        gemm_node_kernel<<<N_NODES, 256, GEMM_SMEM>>>(x, l);
        edge_kernel<<<N_NODES, 256>>>(ea, lng, lnb, ei, out, l);
    }
}